// round 3
// baseline (speedup 1.0000x reference)
#include <cuda_runtime.h>

// Inputs (metadata order):
// 0: dist_mat   float32  [4096*4096]
// 1: vector_mat float32  [4096*4096*3]
// 2: forces_out float32  [4096*3]
// 3: params     float32  [N_ANGLES*2]  (k0, theta0)
// 4: coord_idx  int32    [N_ANGLES*3]  (a1, a2, a3)
// 5: calc_energy int32   [1]
// 6: calc_forces int32   [1]
// Output: out[0] = energy, out[1 .. 1+3*N_ATOMS) = forces (row-major atom,xyz)

__global__ void init_out_kernel(float* __restrict__ out,
                                const float* __restrict__ forces_in,
                                int n_forces) {
    int i = blockIdx.x * blockDim.x + threadIdx.x;
    if (i == 0) out[0] = 0.0f;
    if (i < n_forces) out[1 + i] = forces_in[i];
}

__global__ void __launch_bounds__(256) angle_kernel(
    const float* __restrict__ dist,
    const float* __restrict__ vec,
    const float* __restrict__ params,
    const int*   __restrict__ cidx,
    const int*   __restrict__ calc_e_p,
    const int*   __restrict__ calc_f_p,
    float*       __restrict__ out,
    int n_angles, int n_atoms)
{
    const int i    = blockIdx.x * blockDim.x + threadIdx.x;
    const int ce   = *calc_e_p;
    const int cf   = *calc_f_p;
    float e = 0.0f;

    if (i < n_angles) {
        const int a1 = cidx[3 * i + 0];
        const int a2 = cidx[3 * i + 1];
        const int a3 = cidx[3 * i + 2];

        const size_t r21 = (size_t)a2 * (size_t)n_atoms + (size_t)a1;
        const size_t r23 = (size_t)a2 * (size_t)n_atoms + (size_t)a3;

        const float v21x = __ldg(vec + 3 * r21 + 0);
        const float v21y = __ldg(vec + 3 * r21 + 1);
        const float v21z = __ldg(vec + 3 * r21 + 2);
        const float v23x = __ldg(vec + 3 * r23 + 0);
        const float v23y = __ldg(vec + 3 * r23 + 1);
        const float v23z = __ldg(vec + 3 * r23 + 2);
        const float d21  = __ldg(dist + r21);
        const float d23  = __ldg(dist + r23);

        const float k0 = params[2 * i + 0];
        const float t0 = params[2 * i + 1];

        float ct = v21x * v23x + v21y * v23y + v21z * v23z;
        ct = fminf(1.0f, fmaxf(-1.0f, ct));

        const float theta = acosf(ct);
        const float dth   = theta - t0;

        if (ce) e = k0 * dth * dth;

        if (cf) {
            const float st   = sqrtf(fmaxf(0.0f, 1.0f - ct * ct));
            const float coef = (st > 0.0f)
                             ? (-2.0f * k0 * dth / fmaxf(st, 1e-12f))
                             : 0.0f;
            const float c21 = coef / d21;
            const float c23 = coef / d23;

            const float f0x = c21 * (ct * v21x - v23x);
            const float f0y = c21 * (ct * v21y - v23y);
            const float f0z = c21 * (ct * v21z - v23z);
            const float f2x = c23 * (ct * v23x - v21x);
            const float f2y = c23 * (ct * v23y - v21y);
            const float f2z = c23 * (ct * v23z - v21z);
            const float f1x = -(f0x + f2x);
            const float f1y = -(f0y + f2y);
            const float f1z = -(f0z + f2z);

            float* forces = out + 1;
            atomicAdd(&forces[3 * a1 + 0], f0x);
            atomicAdd(&forces[3 * a1 + 1], f0y);
            atomicAdd(&forces[3 * a1 + 2], f0z);
            atomicAdd(&forces[3 * a2 + 0], f1x);
            atomicAdd(&forces[3 * a2 + 1], f1y);
            atomicAdd(&forces[3 * a2 + 2], f1z);
            atomicAdd(&forces[3 * a3 + 0], f2x);
            atomicAdd(&forces[3 * a3 + 1], f2y);
            atomicAdd(&forces[3 * a3 + 2], f2z);
        }
    }

    // Hierarchical energy reduction: warp shuffle -> shared -> one atomic/block.
    if (ce) {
        #pragma unroll
        for (int off = 16; off > 0; off >>= 1)
            e += __shfl_down_sync(0xffffffffu, e, off);

        __shared__ float warp_sums[8];
        const int lane = threadIdx.x & 31;
        const int wid  = threadIdx.x >> 5;
        if (lane == 0) warp_sums[wid] = e;
        __syncthreads();

        if (wid == 0) {
            e = (lane < (int)(blockDim.x >> 5)) ? warp_sums[lane] : 0.0f;
            #pragma unroll
            for (int off = 4; off > 0; off >>= 1)
                e += __shfl_down_sync(0xffffffffu, e, off);
            if (lane == 0) atomicAdd(out, e);
        }
    }
}

extern "C" void kernel_launch(void* const* d_in, const int* in_sizes, int n_in,
                              void* d_out, int out_size) {
    const float* dist   = (const float*)d_in[0];
    const float* vec    = (const float*)d_in[1];
    const float* f_in   = (const float*)d_in[2];
    const float* params = (const float*)d_in[3];
    const int*   cidx   = (const int*)  d_in[4];
    const int*   ce     = (const int*)  d_in[5];
    const int*   cf     = (const int*)  d_in[6];
    float*       out    = (float*)d_out;

    const int n_angles = in_sizes[4] / 3;
    const int n_forces = in_sizes[2];          // 3 * N_ATOMS
    const int n_atoms  = n_forces / 3;

    {
        const int threads = 256;
        const int blocks  = (n_forces + threads) / threads; // covers energy slot too
        init_out_kernel<<<blocks, threads>>>(out, f_in, n_forces);
    }
    {
        const int threads = 256;
        const int blocks  = (n_angles + threads - 1) / threads;
        angle_kernel<<<blocks, threads>>>(dist, vec, params, cidx, ce, cf,
                                          out, n_angles, n_atoms);
    }
}

// round 4
// speedup vs baseline: 1.0138x; 1.0138x over previous
#include <cuda_runtime.h>

// Inputs (metadata order):
// 0: dist_mat   float32  [4096*4096]
// 1: vector_mat float32  [4096*4096*3]
// 2: forces_out float32  [4096*3]
// 3: params     float32  [N_ANGLES*2]  (k0, theta0)
// 4: coord_idx  int32    [N_ANGLES*3]  (a1, a2, a3)
// 5: calc_energy int32   [1]
// 6: calc_forces int32   [1]
// Output: out[0] = energy, out[1 .. 1+3*N_ATOMS) = forces (row-major atom,xyz)

__global__ void init_out_kernel(float* __restrict__ out,
                                const float* __restrict__ forces_in,
                                int n_forces) {
    int i = blockIdx.x * blockDim.x + threadIdx.x;
    if (i == 0) out[0] = 0.0f;
    if (i < n_forces) out[1 + i] = forces_in[i];
}

__global__ void __launch_bounds__(256) angle_kernel(
    const float* __restrict__ dist,
    const float* __restrict__ vec,
    const float* __restrict__ params,
    const int*   __restrict__ cidx,
    const int*   __restrict__ calc_e_p,
    const int*   __restrict__ calc_f_p,
    float*       __restrict__ out,
    int n_angles, int n_atoms)
{
    const int i    = blockIdx.x * blockDim.x + threadIdx.x;
    const int ce   = *calc_e_p;
    const int cf   = *calc_f_p;
    float e = 0.0f;

    if (i < n_angles) {
        const int a1 = cidx[3 * i + 0];
        const int a2 = cidx[3 * i + 1];
        const int a3 = cidx[3 * i + 2];

        const size_t r21 = (size_t)a2 * (size_t)n_atoms + (size_t)a1;
        const size_t r23 = (size_t)a2 * (size_t)n_atoms + (size_t)a3;

        const float v21x = __ldg(vec + 3 * r21 + 0);
        const float v21y = __ldg(vec + 3 * r21 + 1);
        const float v21z = __ldg(vec + 3 * r21 + 2);
        const float v23x = __ldg(vec + 3 * r23 + 0);
        const float v23y = __ldg(vec + 3 * r23 + 1);
        const float v23z = __ldg(vec + 3 * r23 + 2);
        const float d21  = __ldg(dist + r21);
        const float d23  = __ldg(dist + r23);

        const float k0 = params[2 * i + 0];
        const float t0 = params[2 * i + 1];

        float ct = v21x * v23x + v21y * v23y + v21z * v23z;
        ct = fminf(1.0f, fmaxf(-1.0f, ct));

        const float theta = acosf(ct);
        const float dth   = theta - t0;

        if (ce) e = k0 * dth * dth;

        if (cf) {
            const float st   = sqrtf(fmaxf(0.0f, 1.0f - ct * ct));
            const float coef = (st > 0.0f)
                             ? (-2.0f * k0 * dth / fmaxf(st, 1e-12f))
                             : 0.0f;
            const float c21 = coef / d21;
            const float c23 = coef / d23;

            const float f0x = c21 * (ct * v21x - v23x);
            const float f0y = c21 * (ct * v21y - v23y);
            const float f0z = c21 * (ct * v21z - v23z);
            const float f2x = c23 * (ct * v23x - v21x);
            const float f2y = c23 * (ct * v23y - v21y);
            const float f2z = c23 * (ct * v23z - v21z);
            const float f1x = -(f0x + f2x);
            const float f1y = -(f0y + f2y);
            const float f1z = -(f0z + f2z);

            float* forces = out + 1;
            atomicAdd(&forces[3 * a1 + 0], f0x);
            atomicAdd(&forces[3 * a1 + 1], f0y);
            atomicAdd(&forces[3 * a1 + 2], f0z);
            atomicAdd(&forces[3 * a2 + 0], f1x);
            atomicAdd(&forces[3 * a2 + 1], f1y);
            atomicAdd(&forces[3 * a2 + 2], f1z);
            atomicAdd(&forces[3 * a3 + 0], f2x);
            atomicAdd(&forces[3 * a3 + 1], f2y);
            atomicAdd(&forces[3 * a3 + 2], f2z);
        }
    }

    // Hierarchical energy reduction: warp shuffle -> shared -> one atomic/block.
    if (ce) {
        #pragma unroll
        for (int off = 16; off > 0; off >>= 1)
            e += __shfl_down_sync(0xffffffffu, e, off);

        __shared__ float warp_sums[8];
        const int lane = threadIdx.x & 31;
        const int wid  = threadIdx.x >> 5;
        if (lane == 0) warp_sums[wid] = e;
        __syncthreads();

        if (wid == 0) {
            e = (lane < (int)(blockDim.x >> 5)) ? warp_sums[lane] : 0.0f;
            #pragma unroll
            for (int off = 4; off > 0; off >>= 1)
                e += __shfl_down_sync(0xffffffffu, e, off);
            if (lane == 0) atomicAdd(out, e);
        }
    }
}

extern "C" void kernel_launch(void* const* d_in, const int* in_sizes, int n_in,
                              void* d_out, int out_size) {
    const float* dist   = (const float*)d_in[0];
    const float* vec    = (const float*)d_in[1];
    const float* f_in   = (const float*)d_in[2];
    const float* params = (const float*)d_in[3];
    const int*   cidx   = (const int*)  d_in[4];
    const int*   ce     = (const int*)  d_in[5];
    const int*   cf     = (const int*)  d_in[6];
    float*       out    = (float*)d_out;

    const int n_angles = in_sizes[4] / 3;
    const int n_forces = in_sizes[2];          // 3 * N_ATOMS
    const int n_atoms  = n_forces / 3;

    {
        const int threads = 256;
        const int blocks  = (n_forces + threads) / threads; // covers energy slot too
        init_out_kernel<<<blocks, threads>>>(out, f_in, n_forces);
    }
    {
        const int threads = 256;
        const int blocks  = (n_angles + threads - 1) / threads;
        angle_kernel<<<blocks, threads>>>(dist, vec, params, cidx, ce, cf,
                                          out, n_angles, n_atoms);
    }
}

// round 5
// speedup vs baseline: 1.0585x; 1.0441x over previous
#include <cuda_runtime.h>

// Inputs (metadata order):
// 0: dist_mat   float32  [4096*4096]
// 1: vector_mat float32  [4096*4096*3]
// 2: forces_out float32  [4096*3]
// 3: params     float32  [N_ANGLES*2]  (k0, theta0)
// 4: coord_idx  int32    [N_ANGLES*3]  (a1, a2, a3)
// 5: calc_energy int32   [1]
// 6: calc_forces int32   [1]
// Output: out[0] = energy, out[1 .. 1+3*N_ATOMS) = forces

#define APT 4        // angles per thread
#define TPB 128      // threads per block

__global__ void init_out_kernel(float* __restrict__ out,
                                const float* __restrict__ forces_in,
                                int n_forces) {
    int i = blockIdx.x * blockDim.x + threadIdx.x;
    if (i == 0) out[0] = 0.0f;
    if (i < n_forces) out[1 + i] = forces_in[i];
}

__global__ void __launch_bounds__(TPB) angle_kernel(
    const float* __restrict__ dist,
    const float* __restrict__ vec,
    const float* __restrict__ params,
    const int*   __restrict__ cidx,
    const int*   __restrict__ calc_e_p,
    const int*   __restrict__ calc_f_p,
    float*       __restrict__ out,
    int n_angles, int n_atoms)
{
    const int t  = blockIdx.x * blockDim.x + threadIdx.x;
    const int j0 = t * APT;
    const int ce = *calc_e_p;
    const int cf = *calc_f_p;
    float e = 0.0f;

    if (j0 < n_angles) {
        int   a1[APT], a2[APT], a3[APT];
        float k0[APT], t0[APT];

        if (j0 + APT <= n_angles) {
            // 16B-aligned vector fetch of 4 angles' indices + params.
            const int4* cp = (const int4*)(cidx + 3 * j0);
            int4 c0 = cp[0], c1 = cp[1], c2 = cp[2];
            a1[0] = c0.x; a2[0] = c0.y; a3[0] = c0.z;
            a1[1] = c0.w; a2[1] = c1.x; a3[1] = c1.y;
            a1[2] = c1.z; a2[2] = c1.w; a3[2] = c2.x;
            a1[3] = c2.y; a2[3] = c2.z; a3[3] = c2.w;
            const float4* pp = (const float4*)(params + 2 * j0);
            float4 p0 = pp[0], p1 = pp[1];
            k0[0] = p0.x; t0[0] = p0.y; k0[1] = p0.z; t0[1] = p0.w;
            k0[2] = p1.x; t0[2] = p1.y; k0[3] = p1.z; t0[3] = p1.w;
        } else {
            #pragma unroll
            for (int u = 0; u < APT; u++) {
                int j = j0 + u;
                if (j < n_angles) {
                    a1[u] = cidx[3 * j + 0];
                    a2[u] = cidx[3 * j + 1];
                    a3[u] = cidx[3 * j + 2];
                    k0[u] = params[2 * j + 0];
                    t0[u] = params[2 * j + 1];
                } else {
                    // Dummy lane: index 0, k0 = 0 -> all contributions are 0.
                    a1[u] = a2[u] = a3[u] = 0;
                    k0[u] = 0.0f; t0[u] = 0.0f;
                }
            }
        }

        // ---- Gather phase: issue all 32 independent LDGs up front ----
        float v21x[APT], v21y[APT], v21z[APT];
        float v23x[APT], v23y[APT], v23z[APT];
        float d21[APT], d23[APT];

        #pragma unroll
        for (int u = 0; u < APT; u++) {
            const size_t r21 = (size_t)a2[u] * (size_t)n_atoms + (size_t)a1[u];
            const size_t r23 = (size_t)a2[u] * (size_t)n_atoms + (size_t)a3[u];
            v21x[u] = __ldg(vec + 3 * r21 + 0);
            v21y[u] = __ldg(vec + 3 * r21 + 1);
            v21z[u] = __ldg(vec + 3 * r21 + 2);
            v23x[u] = __ldg(vec + 3 * r23 + 0);
            v23y[u] = __ldg(vec + 3 * r23 + 1);
            v23z[u] = __ldg(vec + 3 * r23 + 2);
            d21[u]  = __ldg(dist + r21);
            d23[u]  = __ldg(dist + r23);
        }

        // ---- Compute + scatter phase ----
        #pragma unroll
        for (int u = 0; u < APT; u++) {
            float ct = v21x[u] * v23x[u] + v21y[u] * v23y[u] + v21z[u] * v23z[u];
            ct = fminf(1.0f, fmaxf(-1.0f, ct));

            const float theta = acosf(ct);
            const float dth   = theta - t0[u];

            e += k0[u] * dth * dth;   // 0 for dummy lanes; masked by ce at reduce

            if (cf) {
                const float st   = sqrtf(fmaxf(0.0f, 1.0f - ct * ct));
                const float coef = (st > 0.0f)
                                 ? (-2.0f * k0[u] * dth / fmaxf(st, 1e-12f))
                                 : 0.0f;
                const float c21 = coef / d21[u];
                const float c23 = coef / d23[u];

                const float f0x = c21 * (ct * v21x[u] - v23x[u]);
                const float f0y = c21 * (ct * v21y[u] - v23y[u]);
                const float f0z = c21 * (ct * v21z[u] - v23z[u]);
                const float f2x = c23 * (ct * v23x[u] - v21x[u]);
                const float f2y = c23 * (ct * v23y[u] - v21y[u]);
                const float f2z = c23 * (ct * v23z[u] - v21z[u]);

                float* forces = out + 1;
                atomicAdd(&forces[3 * a1[u] + 0], f0x);
                atomicAdd(&forces[3 * a1[u] + 1], f0y);
                atomicAdd(&forces[3 * a1[u] + 2], f0z);
                atomicAdd(&forces[3 * a2[u] + 0], -(f0x + f2x));
                atomicAdd(&forces[3 * a2[u] + 1], -(f0y + f2y));
                atomicAdd(&forces[3 * a2[u] + 2], -(f0z + f2z));
                atomicAdd(&forces[3 * a3[u] + 0], f2x);
                atomicAdd(&forces[3 * a3[u] + 1], f2y);
                atomicAdd(&forces[3 * a3[u] + 2], f2z);
            }
        }
    }

    // Hierarchical energy reduction: warp shuffle -> shared -> one atomic/block.
    if (ce) {
        #pragma unroll
        for (int off = 16; off > 0; off >>= 1)
            e += __shfl_down_sync(0xffffffffu, e, off);

        __shared__ float warp_sums[TPB / 32];
        const int lane = threadIdx.x & 31;
        const int wid  = threadIdx.x >> 5;
        if (lane == 0) warp_sums[wid] = e;
        __syncthreads();

        if (wid == 0) {
            e = (lane < TPB / 32) ? warp_sums[lane] : 0.0f;
            #pragma unroll
            for (int off = (TPB / 64); off > 0; off >>= 1)
                e += __shfl_down_sync(0xffffffffu, e, off);
            if (lane == 0) atomicAdd(out, e);
        }
    }
}

extern "C" void kernel_launch(void* const* d_in, const int* in_sizes, int n_in,
                              void* d_out, int out_size) {
    const float* dist   = (const float*)d_in[0];
    const float* vec    = (const float*)d_in[1];
    const float* f_in   = (const float*)d_in[2];
    const float* params = (const float*)d_in[3];
    const int*   cidx   = (const int*)  d_in[4];
    const int*   ce     = (const int*)  d_in[5];
    const int*   cf     = (const int*)  d_in[6];
    float*       out    = (float*)d_out;

    const int n_angles = in_sizes[4] / 3;
    const int n_forces = in_sizes[2];
    const int n_atoms  = n_forces / 3;

    {
        const int threads = 256;
        const int blocks  = (n_forces + threads) / threads;
        init_out_kernel<<<blocks, threads>>>(out, f_in, n_forces);
    }
    {
        const int per_block = TPB * APT;
        const int blocks    = (n_angles + per_block - 1) / per_block;
        angle_kernel<<<blocks, TPB>>>(dist, vec, params, cidx, ce, cf,
                                      out, n_angles, n_atoms);
    }
}

// round 6
// speedup vs baseline: 1.3754x; 1.2994x over previous
#include <cuda_runtime.h>

// Inputs (metadata order):
// 0: dist_mat   float32  [4096*4096]
// 1: vector_mat float32  [4096*4096*3]
// 2: forces_out float32  [4096*3]
// 3: params     float32  [N_ANGLES*2]  (k0, theta0)
// 4: coord_idx  int32    [N_ANGLES*3]  (a1, a2, a3)
// 5: calc_energy int32   [1]
// 6: calc_forces int32   [1]
// Output: out[0] = energy, out[1 .. 1+3*N_ATOMS) = forces

#define APT 2        // angles per thread
#define TPB 256      // threads per block

__global__ void init_out_kernel(float* __restrict__ out,
                                const float* __restrict__ forces_in,
                                int n_forces) {
    int i = blockIdx.x * blockDim.x + threadIdx.x;
    if (i == 0) out[0] = 0.0f;
    if (i < n_forces) out[1 + i] = forces_in[i];
}

// Branchless 12B gather of vec row r via two 8B-aligned float2 loads.
// Byte offset 12r: r even -> lo=(x,y)@3r,   hi=(z,w)@3r+2
//                  r odd  -> lo=(w,x)@3r-1, hi=(y,z)@3r+1
__device__ __forceinline__ void load_vec3(const float* __restrict__ vec,
                                          size_t r, float& x, float& y, float& z) {
    const int odd = (int)(r & 1);
    const float2 lo = __ldg((const float2*)(vec + 3 * r - odd));
    const float2 hi = __ldg((const float2*)(vec + 3 * r + 2 - odd));
    x = odd ? lo.y : lo.x;
    y = odd ? hi.x : lo.y;
    z = odd ? hi.y : hi.x;
}

// Branchless force scatter: one red.v2.f32 on the 8B-aligned pair + one scalar.
// base = out + 1 + 3*a ; byte addr of base rel. d_out = 4 + 12a:
//   a odd  -> base 8B-aligned      -> v2 on (x,y), scalar z
//   a even -> base+1 is 8B-aligned -> v2 on (y,z), scalar x
__device__ __forceinline__ void red_force3(float* base, int a,
                                           float fx, float fy, float fz) {
    const int odd = a & 1;
    float* pv = base + (odd ? 0 : 1);
    const float v0 = odd ? fx : fy;
    const float v1 = odd ? fy : fz;
    float* ps = base + (odd ? 2 : 0);
    const float sv = odd ? fz : fx;
    asm volatile("red.global.add.v2.f32 [%0], {%1, %2};"
                 :: "l"(pv), "f"(v0), "f"(v1) : "memory");
    atomicAdd(ps, sv);
}

__global__ void __launch_bounds__(TPB) angle_kernel(
    const float* __restrict__ dist,
    const float* __restrict__ vec,
    const float* __restrict__ params,
    const int*   __restrict__ cidx,
    const int*   __restrict__ calc_e_p,
    const int*   __restrict__ calc_f_p,
    float*       __restrict__ out,
    int n_angles, int n_atoms)
{
    const int t  = blockIdx.x * blockDim.x + threadIdx.x;
    const int j0 = t * APT;
    const int ce = *calc_e_p;
    const int cf = *calc_f_p;
    float e = 0.0f;

    if (j0 < n_angles) {
        int   a1[APT], a2[APT], a3[APT];
        float k0[APT], t0[APT];

        if (j0 + APT <= n_angles) {
            // 6 ints @ 8B alignment (24B per 2 angles), 4 floats @ 16B.
            const int2* cp = (const int2*)(cidx + 3 * j0);
            int2 c0 = cp[0], c1 = cp[1], c2 = cp[2];
            a1[0] = c0.x; a2[0] = c0.y; a3[0] = c1.x;
            a1[1] = c1.y; a2[1] = c2.x; a3[1] = c2.y;
            const float4 p = *(const float4*)(params + 2 * j0);
            k0[0] = p.x; t0[0] = p.y; k0[1] = p.z; t0[1] = p.w;
        } else {
            #pragma unroll
            for (int u = 0; u < APT; u++) {
                int j = j0 + u;
                if (j < n_angles) {
                    a1[u] = cidx[3 * j + 0];
                    a2[u] = cidx[3 * j + 1];
                    a3[u] = cidx[3 * j + 2];
                    k0[u] = params[2 * j + 0];
                    t0[u] = params[2 * j + 1];
                } else {
                    a1[u] = a2[u] = a3[u] = 0;
                    k0[u] = 0.0f; t0[u] = 0.0f;
                }
            }
        }

        // ---- Gather phase: 12 independent LDGs (4x LDG.64 + 2x LDG.32 per angle) ----
        float v21x[APT], v21y[APT], v21z[APT];
        float v23x[APT], v23y[APT], v23z[APT];
        float d21[APT], d23[APT];

        #pragma unroll
        for (int u = 0; u < APT; u++) {
            const size_t r21 = (size_t)a2[u] * (size_t)n_atoms + (size_t)a1[u];
            const size_t r23 = (size_t)a2[u] * (size_t)n_atoms + (size_t)a3[u];
            load_vec3(vec, r21, v21x[u], v21y[u], v21z[u]);
            load_vec3(vec, r23, v23x[u], v23y[u], v23z[u]);
            d21[u] = __ldg(dist + r21);
            d23[u] = __ldg(dist + r23);
        }

        // ---- Compute + scatter phase ----
        #pragma unroll
        for (int u = 0; u < APT; u++) {
            float ct = v21x[u] * v23x[u] + v21y[u] * v23y[u] + v21z[u] * v23z[u];
            ct = fminf(1.0f, fmaxf(-1.0f, ct));

            const float theta = acosf(ct);
            const float dth   = theta - t0[u];

            e += k0[u] * dth * dth;

            if (cf) {
                const float st   = sqrtf(fmaxf(0.0f, 1.0f - ct * ct));
                const float coef = (st > 0.0f)
                                 ? (-2.0f * k0[u] * dth / fmaxf(st, 1e-12f))
                                 : 0.0f;
                const float c21 = coef / d21[u];
                const float c23 = coef / d23[u];

                const float f0x = c21 * (ct * v21x[u] - v23x[u]);
                const float f0y = c21 * (ct * v21y[u] - v23y[u]);
                const float f0z = c21 * (ct * v21z[u] - v23z[u]);
                const float f2x = c23 * (ct * v23x[u] - v21x[u]);
                const float f2y = c23 * (ct * v23y[u] - v21y[u]);
                const float f2z = c23 * (ct * v23z[u] - v21z[u]);

                float* forces = out + 1;
                red_force3(forces + 3 * a1[u], a1[u], f0x, f0y, f0z);
                red_force3(forces + 3 * a2[u], a2[u],
                           -(f0x + f2x), -(f0y + f2y), -(f0z + f2z));
                red_force3(forces + 3 * a3[u], a3[u], f2x, f2y, f2z);
            }
        }
    }

    // Hierarchical energy reduction: warp shuffle -> shared -> one atomic/block.
    if (ce) {
        #pragma unroll
        for (int off = 16; off > 0; off >>= 1)
            e += __shfl_down_sync(0xffffffffu, e, off);

        __shared__ float warp_sums[TPB / 32];
        const int lane = threadIdx.x & 31;
        const int wid  = threadIdx.x >> 5;
        if (lane == 0) warp_sums[wid] = e;
        __syncthreads();

        if (wid == 0) {
            e = (lane < TPB / 32) ? warp_sums[lane] : 0.0f;
            #pragma unroll
            for (int off = (TPB / 64); off > 0; off >>= 1)
                e += __shfl_down_sync(0xffffffffu, e, off);
            if (lane == 0) atomicAdd(out, e);
        }
    }
}

extern "C" void kernel_launch(void* const* d_in, const int* in_sizes, int n_in,
                              void* d_out, int out_size) {
    const float* dist   = (const float*)d_in[0];
    const float* vec    = (const float*)d_in[1];
    const float* f_in   = (const float*)d_in[2];
    const float* params = (const float*)d_in[3];
    const int*   cidx   = (const int*)  d_in[4];
    const int*   ce     = (const int*)  d_in[5];
    const int*   cf     = (const int*)  d_in[6];
    float*       out    = (float*)d_out;

    const int n_angles = in_sizes[4] / 3;
    const int n_forces = in_sizes[2];
    const int n_atoms  = n_forces / 3;

    {
        const int threads = 256;
        const int blocks  = (n_forces + threads) / threads;
        init_out_kernel<<<blocks, threads>>>(out, f_in, n_forces);
    }
    {
        const int per_block = TPB * APT;
        const int blocks    = (n_angles + per_block - 1) / per_block;
        angle_kernel<<<blocks, TPB>>>(dist, vec, params, cidx, ce, cf,
                                      out, n_angles, n_atoms);
    }
}

// round 8
// speedup vs baseline: 1.3884x; 1.0094x over previous
#include <cuda_runtime.h>

// Inputs (metadata order):
// 0: dist_mat   float32  [4096*4096]
// 1: vector_mat float32  [4096*4096*3]
// 2: forces_out float32  [4096*3]
// 3: params     float32  [N_ANGLES*2]  (k0, theta0)
// 4: coord_idx  int32    [N_ANGLES*3]  (a1, a2, a3)
// 5: calc_energy int32   [1]
// 6: calc_forces int32   [1]
// Output: out[0] = energy, out[1 .. 1+3*N_ATOMS) = forces

#define TPB 256      // threads per block, 1 angle per thread

__global__ void init_out_kernel(float* __restrict__ out,
                                const float* __restrict__ forces_in,
                                int n_forces) {
    int i = blockIdx.x * blockDim.x + threadIdx.x;
    if (i == 0) out[0] = 0.0f;
    if (i < n_forces) out[1 + i] = forces_in[i];
}

// Create an evict_last L2 policy register (fraction 1.0).
__device__ __forceinline__ unsigned long long make_evict_last_policy() {
    unsigned long long pol;
    asm("createpolicy.fractional.L2::evict_last.b64 %0, 1.0;" : "=l"(pol));
    return pol;
}

// dist: 64MB, fits in L2 entirely -> pin with evict_last via cache_hint.
__device__ __forceinline__ float ldg_dist(const float* p, unsigned long long pol) {
    float v;
    asm volatile("ld.global.nc.L2::cache_hint.f32 %0, [%1], %2;"
                 : "=f"(v) : "l"(p), "l"(pol));
    return v;
}

// vec: 192MB, default policy (competes for remaining L2).
__device__ __forceinline__ float2 ldg_v2(const float* p) {
    float2 v;
    asm volatile("ld.global.nc.v2.f32 {%0, %1}, [%2];"
                 : "=f"(v.x), "=f"(v.y) : "l"(p));
    return v;
}

// Branchless 12B gather of vec row r via two 8B-aligned float2 loads.
__device__ __forceinline__ void load_vec3(const float* __restrict__ vec,
                                          size_t r, float& x, float& y, float& z) {
    const int odd = (int)(r & 1);
    const float2 lo = ldg_v2(vec + 3 * r - odd);
    const float2 hi = ldg_v2(vec + 3 * r + 2 - odd);
    x = odd ? lo.y : lo.x;
    y = odd ? hi.x : lo.y;
    z = odd ? hi.y : hi.x;
}

// Branchless force scatter: one red.v2.f32 on the 8B-aligned pair + one scalar.
// base = out + 1 + 3*a ; byte addr of base rel. d_out = 4 + 12a:
//   a odd  -> base 8B-aligned      -> v2 on (x,y), scalar z
//   a even -> base+1 is 8B-aligned -> v2 on (y,z), scalar x
__device__ __forceinline__ void red_force3(float* base, int a,
                                           float fx, float fy, float fz) {
    const int odd = a & 1;
    float* pv = base + (odd ? 0 : 1);
    const float v0 = odd ? fx : fy;
    const float v1 = odd ? fy : fz;
    float* ps = base + (odd ? 2 : 0);
    const float sv = odd ? fz : fx;
    asm volatile("red.global.add.v2.f32 [%0], {%1, %2};"
                 :: "l"(pv), "f"(v0), "f"(v1) : "memory");
    atomicAdd(ps, sv);
}

__global__ void __launch_bounds__(TPB) angle_kernel(
    const float* __restrict__ dist,
    const float* __restrict__ vec,
    const float* __restrict__ params,
    const int*   __restrict__ cidx,
    const int*   __restrict__ calc_e_p,
    const int*   __restrict__ calc_f_p,
    float*       __restrict__ out,
    int n_angles, int n_atoms)
{
    const int j  = blockIdx.x * blockDim.x + threadIdx.x;
    const int ce = *calc_e_p;
    const int cf = *calc_f_p;
    float e = 0.0f;

    if (j < n_angles) {
        const unsigned long long pol = make_evict_last_policy();

        // Indices: 12B at cidx+3j, same parity trick as vec3 (two 8B loads).
        const int jodd = j & 1;
        const int2 clo = *(const int2*)(cidx + 3 * j - jodd);
        const int2 chi = *(const int2*)(cidx + 3 * j + 2 - jodd);
        const int a1 = jodd ? clo.y : clo.x;
        const int a2 = jodd ? chi.x : clo.y;
        const int a3 = jodd ? chi.y : chi.x;

        // Params: 8B aligned always.
        const float2 p = *(const float2*)(params + 2 * j);
        const float k0 = p.x, t0 = p.y;

        const size_t r21 = (size_t)a2 * (size_t)n_atoms + (size_t)a1;
        const size_t r23 = (size_t)a2 * (size_t)n_atoms + (size_t)a3;

        // Front-batched gathers: 4x LDG.64 (vec) + 2x LDG.32 (dist, L2-pinned).
        float v21x, v21y, v21z, v23x, v23y, v23z;
        load_vec3(vec, r21, v21x, v21y, v21z);
        load_vec3(vec, r23, v23x, v23y, v23z);
        const float d21 = ldg_dist(dist + r21, pol);
        const float d23 = ldg_dist(dist + r23, pol);

        float ct = v21x * v23x + v21y * v23y + v21z * v23z;
        ct = fminf(1.0f, fmaxf(-1.0f, ct));

        const float theta = acosf(ct);
        const float dth   = theta - t0;

        e = k0 * dth * dth;

        if (cf) {
            const float st   = sqrtf(fmaxf(0.0f, 1.0f - ct * ct));
            const float coef = (st > 0.0f)
                             ? (-2.0f * k0 * dth / fmaxf(st, 1e-12f))
                             : 0.0f;
            const float c21 = coef / d21;
            const float c23 = coef / d23;

            const float f0x = c21 * (ct * v21x - v23x);
            const float f0y = c21 * (ct * v21y - v23y);
            const float f0z = c21 * (ct * v21z - v23z);
            const float f2x = c23 * (ct * v23x - v21x);
            const float f2y = c23 * (ct * v23y - v21y);
            const float f2z = c23 * (ct * v23z - v21z);

            float* forces = out + 1;
            red_force3(forces + 3 * a1, a1, f0x, f0y, f0z);
            red_force3(forces + 3 * a2, a2,
                       -(f0x + f2x), -(f0y + f2y), -(f0z + f2z));
            red_force3(forces + 3 * a3, a3, f2x, f2y, f2z);
        }
    }

    // Hierarchical energy reduction: warp shuffle -> shared -> one atomic/block.
    if (ce) {
        #pragma unroll
        for (int off = 16; off > 0; off >>= 1)
            e += __shfl_down_sync(0xffffffffu, e, off);

        __shared__ float warp_sums[TPB / 32];
        const int lane = threadIdx.x & 31;
        const int wid  = threadIdx.x >> 5;
        if (lane == 0) warp_sums[wid] = e;
        __syncthreads();

        if (wid == 0) {
            e = (lane < TPB / 32) ? warp_sums[lane] : 0.0f;
            #pragma unroll
            for (int off = (TPB / 64); off > 0; off >>= 1)
                e += __shfl_down_sync(0xffffffffu, e, off);
            if (lane == 0) atomicAdd(out, e);
        }
    }
}

extern "C" void kernel_launch(void* const* d_in, const int* in_sizes, int n_in,
                              void* d_out, int out_size) {
    const float* dist   = (const float*)d_in[0];
    const float* vec    = (const float*)d_in[1];
    const float* f_in   = (const float*)d_in[2];
    const float* params = (const float*)d_in[3];
    const int*   cidx   = (const int*)  d_in[4];
    const int*   ce     = (const int*)  d_in[5];
    const int*   cf     = (const int*)  d_in[6];
    float*       out    = (float*)d_out;

    const int n_angles = in_sizes[4] / 3;
    const int n_forces = in_sizes[2];
    const int n_atoms  = n_forces / 3;

    {
        const int threads = 256;
        const int blocks  = (n_forces + threads) / threads;
        init_out_kernel<<<blocks, threads>>>(out, f_in, n_forces);
    }
    {
        const int blocks = (n_angles + TPB - 1) / TPB;
        angle_kernel<<<blocks, TPB>>>(dist, vec, params, cidx, ce, cf,
                                      out, n_angles, n_atoms);
    }
}